// round 8
// baseline (speedup 1.0000x reference)
#include <cuda_runtime.h>
#include <cuda_fp16.h>

#define BB 128
#define PP 4096
#define NN 64

// One fused kernel. Block = (batch b, center-quarter cq): 256 threads = 8 warps.
//   warp & 3  -> 4-center group within the quarter (coeffs in regs)
//   warp >> 2 -> point half (2 x 2048 points)
// grid = 512; __launch_bounds__(256,4) -> 32 warps/SM, single wave.
// q[n](x) = K + a0*x0^2 + b0*x0 + a1*x1^2 + b1*x1,  exp(-dist) = EX2(q)
// Fast path (uniform a0/a1 within the warp's 4 centers):
//   q = (K_n + B0_n*x0 + B1_n*x1) + base(x);  EX2 evaluated as f16x2 pairs
//   (one MUFU op per TWO exponentials) -- halves MUFU port pressure.
__global__ __launch_bounds__(256, 4) void slayer_fused(
    const float4* __restrict__ batch,    // [B, P/2] of float4 (2 points, D=2)
    const float2* __restrict__ mask,     // [B, P/2] of float2
    const float*  __restrict__ centers,  // [N, D]
    const float*  __restrict__ sharp,    // [N, D]
    float*        __restrict__ out)      // [B, N]
{
    const int b    = blockIdx.x >> 2;
    const int cq   = blockIdx.x & 3;     // centers [16*cq, 16*cq+16)
    const int tid  = threadIdx.x;
    const int warp = tid >> 5;
    const int lane = tid & 31;
    const int cg   = warp & 3;           // 4-center group within quarter
    const int half = warp >> 2;          // point half

    const float L = 1.4426950408889634f;  // log2(e)
    const int n0 = 16 * cq + 4 * cg;
    float A0[4], B0[4], A1[4], B1[4], KK[4], acc[4];
#pragma unroll
    for (int j = 0; j < 4; j++) {
        const int n = n0 + j;
        const float c0 = __ldg(centers + 2 * n);
        const float c1 = __ldg(centers + 2 * n + 1);
        const float s0 = __ldg(sharp + 2 * n);
        const float s1 = __ldg(sharp + 2 * n + 1);
        const float a0 = -L * s0 * s0;
        const float a1 = -L * s1 * s1;
        A0[j] = a0;
        A1[j] = a1;
        B0[j] = -2.0f * a0 * c0;
        B1[j] = -2.0f * a1 * c1;
        KK[j] = a0 * c0 * c0 + a1 * c1 * c1;
        acc[j] = 0.0f;
    }

    // Per-warp uniformity of the quadratic coefficients (warp-coherent branch)
    const bool uniform = (A0[1] == A0[0]) & (A0[2] == A0[0]) & (A0[3] == A0[0]) &
                         (A1[1] == A1[0]) & (A1[2] == A1[0]) & (A1[3] == A1[0]);

    const float4* bp = batch + (size_t)b * (PP / 2) + half * (PP / 4);
    const float2* mp = mask  + (size_t)b * (PP / 2) + half * (PP / 4);

    constexpr int ITERS = (PP / 4) / 32;   // 32 iterations, 2 points each

    if (uniform) {
        const float a0 = A0[0], a1 = A1[0];
#pragma unroll 2
        for (int it = 0; it < ITERS; it++) {
            const int p = it * 32 + lane;
            const float4 x = __ldg(bp + p);    // point A=(x,y), point B=(z,w)
            const float2 m = __ldg(mp + p);

            const float basea = fmaf(a0 * x.x, x.x, (a1 * x.y) * x.y);
            const float baseb = fmaf(a0 * x.z, x.z, (a1 * x.w) * x.w);

#pragma unroll
            for (int j = 0; j < 4; j++) {
                float qa = fmaf(B0[j], x.x, KK[j]);
                qa = fmaf(B1[j], x.y, qa);
                qa += basea;
                float qb = fmaf(B0[j], x.z, KK[j]);
                qb = fmaf(B1[j], x.w, qb);
                qb += baseb;
                // Two exponentials in ONE MUFU op (f16x2)
                const __half2 h  = __float22half2_rn(make_float2(qa, qb));
                const __half2 e2 = h2exp2(h);
                const float2  e  = __half22float2(e2);
                acc[j] = fmaf(m.x, e.x, acc[j]);
                acc[j] = fmaf(m.y, e.y, acc[j]);
            }
        }
    } else {
        // General path: full per-center quadratic, f32 EX2 (exactness first)
#pragma unroll 2
        for (int it = 0; it < ITERS; it++) {
            const int p = it * 32 + lane;
            const float4 x = __ldg(bp + p);
            const float2 m = __ldg(mp + p);

            const float xa0 = x.x * x.x, xa1 = x.y * x.y;
            const float xb0 = x.z * x.z, xb1 = x.w * x.w;

#pragma unroll
            for (int j = 0; j < 4; j++) {
                float qa = KK[j];
                qa = fmaf(A0[j], xa0, qa);
                qa = fmaf(B0[j], x.x, qa);
                qa = fmaf(A1[j], xa1, qa);
                qa = fmaf(B1[j], x.y, qa);
                float qb = KK[j];
                qb = fmaf(A0[j], xb0, qb);
                qb = fmaf(B0[j], x.z, qb);
                qb = fmaf(A1[j], xb1, qb);
                qb = fmaf(B1[j], x.w, qb);
                float ea, eb;
                asm("ex2.approx.ftz.f32 %0, %1;" : "=f"(ea) : "f"(qa));
                asm("ex2.approx.ftz.f32 %0, %1;" : "=f"(eb) : "f"(qb));
                acc[j] = fmaf(m.x, ea, acc[j]);
                acc[j] = fmaf(m.y, eb, acc[j]);
            }
        }
    }

    // Reduce over the 32 point-lanes
#pragma unroll
    for (int off = 16; off > 0; off >>= 1) {
#pragma unroll
        for (int j = 0; j < 4; j++)
            acc[j] += __shfl_xor_sync(0xffffffffu, acc[j], off);
    }

    // Combine the two point-halves deterministically via shared memory
    __shared__ float partial[2][16];
    if (lane == 0) {
#pragma unroll
        for (int j = 0; j < 4; j++)
            partial[half][4 * cg + j] = acc[j];
    }
    __syncthreads();

    if (tid < 16)
        out[b * NN + 16 * cq + tid] = partial[0][tid] + partial[1][tid];
}

extern "C" void kernel_launch(void* const* d_in, const int* in_sizes, int n_in,
                              void* d_out, int out_size) {
    const float* batch   = (const float*)d_in[0];   // [B,P,D] f32
    const float* mask    = (const float*)d_in[1];   // [B,P]   f32
    const float* centers = (const float*)d_in[2];   // [N,D]   f32
    const float* sharp   = (const float*)d_in[3];   // [N,D]   f32
    float* out = (float*)d_out;                     // [B,N]   f32

    slayer_fused<<<BB * 4, 256>>>((const float4*)batch, (const float2*)mask,
                                  centers, sharp, out);
}

// round 9
// speedup vs baseline: 1.2397x; 1.2397x over previous
#include <cuda_runtime.h>

#define BB 128
#define PP 4096
#define NN 64

// One fused kernel. Block = (batch b, center-quarter cq): 256 threads = 8 warps.
//   warp & 3  -> 4-center group within the quarter (coeffs in regs)
//   warp >> 2 -> point half (2 x 2048 points)
// grid = 512; __launch_bounds__(256,4) -> 32 warps/SM, single wave.
// Loads are software-pipelined (double-buffered) so L2-latency misses are
// covered by the previous iteration's FMA/EX2 work.
// q[n](x) = K + a0*x0^2 + b0*x0 + a1*x1^2 + b1*x1,  exp(-dist) = EX2(q)
__global__ __launch_bounds__(256, 4) void slayer_fused(
    const float4* __restrict__ batch,    // [B, P/2] of float4 (2 points, D=2)
    const float2* __restrict__ mask,     // [B, P/2] of float2
    const float*  __restrict__ centers,  // [N, D]
    const float*  __restrict__ sharp,    // [N, D]
    float*        __restrict__ out)      // [B, N]
{
    const int b    = blockIdx.x >> 2;
    const int cq   = blockIdx.x & 3;     // centers [16*cq, 16*cq+16)
    const int tid  = threadIdx.x;
    const int warp = tid >> 5;
    const int lane = tid & 31;
    const int cg   = warp & 3;           // 4-center group within quarter
    const int half = warp >> 2;          // point half

    const float L = 1.4426950408889634f;  // log2(e)
    const int n0 = 16 * cq + 4 * cg;
    float A0[4], B0[4], A1[4], B1[4], KK[4], acc[4];
#pragma unroll
    for (int j = 0; j < 4; j++) {
        const int n = n0 + j;
        const float c0 = __ldg(centers + 2 * n);
        const float c1 = __ldg(centers + 2 * n + 1);
        const float s0 = __ldg(sharp + 2 * n);
        const float s1 = __ldg(sharp + 2 * n + 1);
        const float a0 = -L * s0 * s0;
        const float a1 = -L * s1 * s1;
        A0[j] = a0;
        A1[j] = a1;
        B0[j] = -2.0f * a0 * c0;
        B1[j] = -2.0f * a1 * c1;
        KK[j] = a0 * c0 * c0 + a1 * c1 * c1;
        acc[j] = 0.0f;
    }

    const bool uniform = (A0[1] == A0[0]) & (A0[2] == A0[0]) & (A0[3] == A0[0]) &
                         (A1[1] == A1[0]) & (A1[2] == A1[0]) & (A1[3] == A1[0]);

    const float4* bpl = batch + (size_t)b * (PP / 2) + half * (PP / 4) + lane;
    const float2* mpl = mask  + (size_t)b * (PP / 2) + half * (PP / 4) + lane;

    constexpr int ITERS = (PP / 4) / 32;   // 32 iterations, 2 points each

    // Software pipeline: prefetch iteration i+1 while computing iteration i.
    float4 xc = __ldg(bpl);
    float2 mc = __ldg(mpl);

    if (uniform) {
        const float a0 = A0[0], a1 = A1[0];
#pragma unroll 2
        for (int it = 0; it < ITERS; it++) {
            float4 xn = xc;
            float2 mn = mc;
            if (it + 1 < ITERS) {
                xn = __ldg(bpl + (it + 1) * 32);
                mn = __ldg(mpl + (it + 1) * 32);
            }

            const float basea = fmaf(a0 * xc.x, xc.x, (a1 * xc.y) * xc.y);
            const float baseb = fmaf(a0 * xc.z, xc.z, (a1 * xc.w) * xc.w);

#pragma unroll
            for (int j = 0; j < 4; j++) {
                float qa = fmaf(B0[j], xc.x, KK[j]);
                qa = fmaf(B1[j], xc.y, qa);
                qa += basea;
                float qb = fmaf(B0[j], xc.z, KK[j]);
                qb = fmaf(B1[j], xc.w, qb);
                qb += baseb;
                float ea, eb;
                asm("ex2.approx.ftz.f32 %0, %1;" : "=f"(ea) : "f"(qa));
                asm("ex2.approx.ftz.f32 %0, %1;" : "=f"(eb) : "f"(qb));
                acc[j] = fmaf(mc.x, ea, acc[j]);
                acc[j] = fmaf(mc.y, eb, acc[j]);
            }
            xc = xn;
            mc = mn;
        }
    } else {
#pragma unroll 2
        for (int it = 0; it < ITERS; it++) {
            float4 xn = xc;
            float2 mn = mc;
            if (it + 1 < ITERS) {
                xn = __ldg(bpl + (it + 1) * 32);
                mn = __ldg(mpl + (it + 1) * 32);
            }

            const float xa0 = xc.x * xc.x, xa1 = xc.y * xc.y;
            const float xb0 = xc.z * xc.z, xb1 = xc.w * xc.w;

#pragma unroll
            for (int j = 0; j < 4; j++) {
                float qa = KK[j];
                qa = fmaf(A0[j], xa0, qa);
                qa = fmaf(B0[j], xc.x, qa);
                qa = fmaf(A1[j], xa1, qa);
                qa = fmaf(B1[j], xc.y, qa);
                float qb = KK[j];
                qb = fmaf(A0[j], xb0, qb);
                qb = fmaf(B0[j], xc.z, qb);
                qb = fmaf(A1[j], xb1, qb);
                qb = fmaf(B1[j], xc.w, qb);
                float ea, eb;
                asm("ex2.approx.ftz.f32 %0, %1;" : "=f"(ea) : "f"(qa));
                asm("ex2.approx.ftz.f32 %0, %1;" : "=f"(eb) : "f"(qb));
                acc[j] = fmaf(mc.x, ea, acc[j]);
                acc[j] = fmaf(mc.y, eb, acc[j]);
            }
            xc = xn;
            mc = mn;
        }
    }

    // Reduce over the 32 point-lanes
#pragma unroll
    for (int off = 16; off > 0; off >>= 1) {
#pragma unroll
        for (int j = 0; j < 4; j++)
            acc[j] += __shfl_xor_sync(0xffffffffu, acc[j], off);
    }

    // Combine the two point-halves deterministically via shared memory
    __shared__ float partial[2][16];
    if (lane == 0) {
#pragma unroll
        for (int j = 0; j < 4; j++)
            partial[half][4 * cg + j] = acc[j];
    }
    __syncthreads();

    if (tid < 16)
        out[b * NN + 16 * cq + tid] = partial[0][tid] + partial[1][tid];
}

extern "C" void kernel_launch(void* const* d_in, const int* in_sizes, int n_in,
                              void* d_out, int out_size) {
    const float* batch   = (const float*)d_in[0];   // [B,P,D] f32
    const float* mask    = (const float*)d_in[1];   // [B,P]   f32
    const float* centers = (const float*)d_in[2];   // [N,D]   f32
    const float* sharp   = (const float*)d_in[3];   // [N,D]   f32
    float* out = (float*)d_out;                     // [B,N]   f32

    slayer_fused<<<BB * 4, 256>>>((const float4*)batch, (const float2*)mask,
                                  centers, sharp, out);
}

// round 10
// speedup vs baseline: 1.4055x; 1.1338x over previous
#include <cuda_runtime.h>

#define BB 128
#define PP 4096
#define NN 64

// One fused kernel. Block = (batch b, center-octet g): 256 threads = 8 warps.
// Each warp sweeps its own 512-point range for the SAME 8 centers
// (coeffs register-resident), 2 points/lane/iter -> 16 independent EX2/iter.
// grid = 1024; __launch_bounds__(256,4) -> 32 warps/SM.
// q[n](x) = K + a0*x0^2 + b0*x0 + a1*x1^2 + b1*x1,  exp(-dist) = EX2(q)
// Uniform fast path (all 8 centers share a0,a1):
//   q = (K_n + B0_n*x0 + B1_n*x1) + base(x),  base = a0*x0^2 + a1*x1^2
__global__ __launch_bounds__(256, 4) void slayer_fused(
    const float4* __restrict__ batch,    // [B, P/2] of float4 (2 points, D=2)
    const float2* __restrict__ mask,     // [B, P/2] of float2
    const float*  __restrict__ centers,  // [N, D]
    const float*  __restrict__ sharp,    // [N, D]
    float*        __restrict__ out)      // [B, N]
{
    const int b    = blockIdx.x >> 3;
    const int g    = blockIdx.x & 7;     // centers [8g, 8g+8)
    const int tid  = threadIdx.x;
    const int warp = tid >> 5;
    const int lane = tid & 31;
    const int n0   = 8 * g;

    __shared__ float partial[8][8];      // [warp][center]

    const float L = 1.4426950408889634f;  // log2(e)

    // Linear coefficients for 8 centers; uniformity check on a0/a1.
    float B0[8], B1[8], KK[8], acc[8];
    float a00 = 0.0f, a10 = 0.0f;
    bool uniform = true;
#pragma unroll
    for (int j = 0; j < 8; j++) {
        const int n = n0 + j;
        const float c0 = __ldg(centers + 2 * n);
        const float c1 = __ldg(centers + 2 * n + 1);
        const float s0 = __ldg(sharp + 2 * n);
        const float s1 = __ldg(sharp + 2 * n + 1);
        const float a0 = -L * s0 * s0;
        const float a1 = -L * s1 * s1;
        if (j == 0) { a00 = a0; a10 = a1; }
        uniform = uniform && (a0 == a00) && (a1 == a10);
        B0[j] = -2.0f * a0 * c0;
        B1[j] = -2.0f * a1 * c1;
        KK[j] = a0 * c0 * c0 + a1 * c1 * c1;
        acc[j] = 0.0f;
    }

    // This warp's 512-point range: 256 float4 entries.
    const float4* bp = batch + (size_t)b * (PP / 2) + warp * 256;
    const float2* mp = mask  + (size_t)b * (PP / 2) + warp * 256;

    constexpr int ITERS = 8;   // 8 iters x 32 lanes x 2 points = 512 points

    if (uniform) {
#pragma unroll 2
        for (int it = 0; it < ITERS; it++) {
            const int p = it * 32 + lane;
            const float4 x = __ldg(bp + p);    // point A=(x,y), point B=(z,w)
            const float2 m = __ldg(mp + p);

            const float basea = fmaf(a00 * x.x, x.x, (a10 * x.y) * x.y);
            const float baseb = fmaf(a00 * x.z, x.z, (a10 * x.w) * x.w);

#pragma unroll
            for (int j = 0; j < 8; j++) {
                float qa = fmaf(B0[j], x.x, KK[j]);
                qa = fmaf(B1[j], x.y, qa);
                qa += basea;
                float qb = fmaf(B0[j], x.z, KK[j]);
                qb = fmaf(B1[j], x.w, qb);
                qb += baseb;
                float ea, eb;
                asm("ex2.approx.ftz.f32 %0, %1;" : "=f"(ea) : "f"(qa));
                asm("ex2.approx.ftz.f32 %0, %1;" : "=f"(eb) : "f"(qb));
                acc[j] = fmaf(m.x, ea, acc[j]);
                acc[j] = fmaf(m.y, eb, acc[j]);
            }
        }

        // Reduce over lanes, stash per-warp partials
#pragma unroll
        for (int off = 16; off > 0; off >>= 1) {
#pragma unroll
            for (int j = 0; j < 8; j++)
                acc[j] += __shfl_xor_sync(0xffffffffu, acc[j], off);
        }
        if (lane == 0) {
#pragma unroll
            for (int j = 0; j < 8; j++)
                partial[warp][j] = acc[j];
        }
    } else {
        // General path (cold): full quadratic, 2 passes of 4 centers.
        for (int pass = 0; pass < 2; pass++) {
            float A0g[4], B0g[4], A1g[4], B1g[4], Kg[4], ac[4];
#pragma unroll
            for (int j = 0; j < 4; j++) {
                const int n = n0 + 4 * pass + j;
                const float c0 = __ldg(centers + 2 * n);
                const float c1 = __ldg(centers + 2 * n + 1);
                const float s0 = __ldg(sharp + 2 * n);
                const float s1 = __ldg(sharp + 2 * n + 1);
                const float a0 = -L * s0 * s0;
                const float a1 = -L * s1 * s1;
                A0g[j] = a0;
                A1g[j] = a1;
                B0g[j] = -2.0f * a0 * c0;
                B1g[j] = -2.0f * a1 * c1;
                Kg[j]  = a0 * c0 * c0 + a1 * c1 * c1;
                ac[j]  = 0.0f;
            }
#pragma unroll 2
            for (int it = 0; it < ITERS; it++) {
                const int p = it * 32 + lane;
                const float4 x = __ldg(bp + p);
                const float2 m = __ldg(mp + p);
                const float xa0 = x.x * x.x, xa1 = x.y * x.y;
                const float xb0 = x.z * x.z, xb1 = x.w * x.w;
#pragma unroll
                for (int j = 0; j < 4; j++) {
                    float qa = Kg[j];
                    qa = fmaf(A0g[j], xa0, qa);
                    qa = fmaf(B0g[j], x.x, qa);
                    qa = fmaf(A1g[j], xa1, qa);
                    qa = fmaf(B1g[j], x.y, qa);
                    float qb = Kg[j];
                    qb = fmaf(A0g[j], xb0, qb);
                    qb = fmaf(B0g[j], x.z, qb);
                    qb = fmaf(A1g[j], xb1, qb);
                    qb = fmaf(B1g[j], x.w, qb);
                    float ea, eb;
                    asm("ex2.approx.ftz.f32 %0, %1;" : "=f"(ea) : "f"(qa));
                    asm("ex2.approx.ftz.f32 %0, %1;" : "=f"(eb) : "f"(qb));
                    ac[j] = fmaf(m.x, ea, ac[j]);
                    ac[j] = fmaf(m.y, eb, ac[j]);
                }
            }
#pragma unroll
            for (int off = 16; off > 0; off >>= 1) {
#pragma unroll
                for (int j = 0; j < 4; j++)
                    ac[j] += __shfl_xor_sync(0xffffffffu, ac[j], off);
            }
            if (lane == 0) {
#pragma unroll
                for (int j = 0; j < 4; j++)
                    partial[warp][4 * pass + j] = ac[j];
            }
        }
    }

    __syncthreads();

    // Combine 8 warp partials -> 8 outputs for this block
    if (tid < 8) {
        float v = 0.0f;
#pragma unroll
        for (int w = 0; w < 8; w++)
            v += partial[w][tid];
        out[b * NN + n0 + tid] = v;
    }
}

extern "C" void kernel_launch(void* const* d_in, const int* in_sizes, int n_in,
                              void* d_out, int out_size) {
    const float* batch   = (const float*)d_in[0];   // [B,P,D] f32
    const float* mask    = (const float*)d_in[1];   // [B,P]   f32
    const float* centers = (const float*)d_in[2];   // [N,D]   f32
    const float* sharp   = (const float*)d_in[3];   // [N,D]   f32
    float* out = (float*)d_out;                     // [B,N]   f32

    slayer_fused<<<BB * 8, 256>>>((const float4*)batch, (const float2*)mask,
                                  centers, sharp, out);
}

// round 11
// speedup vs baseline: 1.4298x; 1.0173x over previous
#include <cuda_runtime.h>

#define BB 128
#define PP 4096
#define NN 64

// One fused kernel. Block = (batch b, center-octet g): 256 threads = 8 warps.
// Each warp sweeps its own 512-point range for the SAME 8 centers
// (coeffs register-resident), 2 points/lane/iter -> 16 independent EX2/iter.
// grid = 1024; __launch_bounds__(256,3) -> 85-reg budget, 24 warps/SM:
// the extra registers let ptxas keep many exp chains + next-iter loads in
// flight across the EX2 latency window (the diagnosed limiter).
// q[n](x) = K + a0*x0^2 + b0*x0 + a1*x1^2 + b1*x1,  exp(-dist) = EX2(q)
// Uniform fast path (all 8 centers share a0,a1):
//   q = (K_n + B0_n*x0 + B1_n*x1) + base(x),  base = a0*x0^2 + a1*x1^2
__global__ __launch_bounds__(256, 3) void slayer_fused(
    const float4* __restrict__ batch,    // [B, P/2] of float4 (2 points, D=2)
    const float2* __restrict__ mask,     // [B, P/2] of float2
    const float*  __restrict__ centers,  // [N, D]
    const float*  __restrict__ sharp,    // [N, D]
    float*        __restrict__ out)      // [B, N]
{
    const int b    = blockIdx.x >> 3;
    const int g    = blockIdx.x & 7;     // centers [8g, 8g+8)
    const int tid  = threadIdx.x;
    const int warp = tid >> 5;
    const int lane = tid & 31;
    const int n0   = 8 * g;

    __shared__ float partial[8][8];      // [warp][center]

    const float L = 1.4426950408889634f;  // log2(e)

    // Linear coefficients for 8 centers; uniformity check on a0/a1.
    float B0[8], B1[8], KK[8], acc[8];
    float a00 = 0.0f, a10 = 0.0f;
    bool uniform = true;
#pragma unroll
    for (int j = 0; j < 8; j++) {
        const int n = n0 + j;
        const float c0 = __ldg(centers + 2 * n);
        const float c1 = __ldg(centers + 2 * n + 1);
        const float s0 = __ldg(sharp + 2 * n);
        const float s1 = __ldg(sharp + 2 * n + 1);
        const float a0 = -L * s0 * s0;
        const float a1 = -L * s1 * s1;
        if (j == 0) { a00 = a0; a10 = a1; }
        uniform = uniform && (a0 == a00) && (a1 == a10);
        B0[j] = -2.0f * a0 * c0;
        B1[j] = -2.0f * a1 * c1;
        KK[j] = a0 * c0 * c0 + a1 * c1 * c1;
        acc[j] = 0.0f;
    }

    // This warp's 512-point range: 256 float4 entries.
    const float4* bp = batch + (size_t)b * (PP / 2) + warp * 256 + lane;
    const float2* mp = mask  + (size_t)b * (PP / 2) + warp * 256 + lane;

    constexpr int ITERS = 8;   // 8 iters x 32 lanes x 2 points = 512 points

    if (uniform) {
#pragma unroll
        for (int it = 0; it < ITERS; it++) {
            const float4 x = __ldg(bp + it * 32);  // A=(x,y), B=(z,w)
            const float2 m = __ldg(mp + it * 32);

            const float basea = fmaf(a00 * x.x, x.x, (a10 * x.y) * x.y);
            const float baseb = fmaf(a00 * x.z, x.z, (a10 * x.w) * x.w);

#pragma unroll
            for (int j = 0; j < 8; j++) {
                float qa = fmaf(B0[j], x.x, KK[j]);
                qa = fmaf(B1[j], x.y, qa);
                qa += basea;
                float qb = fmaf(B0[j], x.z, KK[j]);
                qb = fmaf(B1[j], x.w, qb);
                qb += baseb;
                float ea, eb;
                asm("ex2.approx.ftz.f32 %0, %1;" : "=f"(ea) : "f"(qa));
                asm("ex2.approx.ftz.f32 %0, %1;" : "=f"(eb) : "f"(qb));
                acc[j] = fmaf(m.x, ea, acc[j]);
                acc[j] = fmaf(m.y, eb, acc[j]);
            }
        }

        // Reduce over lanes, stash per-warp partials
#pragma unroll
        for (int off = 16; off > 0; off >>= 1) {
#pragma unroll
            for (int j = 0; j < 8; j++)
                acc[j] += __shfl_xor_sync(0xffffffffu, acc[j], off);
        }
        if (lane == 0) {
#pragma unroll
            for (int j = 0; j < 8; j++)
                partial[warp][j] = acc[j];
        }
    } else {
        // General path (cold): full quadratic, 2 passes of 4 centers.
        for (int pass = 0; pass < 2; pass++) {
            float A0g[4], B0g[4], A1g[4], B1g[4], Kg[4], ac[4];
#pragma unroll
            for (int j = 0; j < 4; j++) {
                const int n = n0 + 4 * pass + j;
                const float c0 = __ldg(centers + 2 * n);
                const float c1 = __ldg(centers + 2 * n + 1);
                const float s0 = __ldg(sharp + 2 * n);
                const float s1 = __ldg(sharp + 2 * n + 1);
                const float a0 = -L * s0 * s0;
                const float a1 = -L * s1 * s1;
                A0g[j] = a0;
                A1g[j] = a1;
                B0g[j] = -2.0f * a0 * c0;
                B1g[j] = -2.0f * a1 * c1;
                Kg[j]  = a0 * c0 * c0 + a1 * c1 * c1;
                ac[j]  = 0.0f;
            }
#pragma unroll 2
            for (int it = 0; it < ITERS; it++) {
                const float4 x = __ldg(bp + it * 32);
                const float2 m = __ldg(mp + it * 32);
                const float xa0 = x.x * x.x, xa1 = x.y * x.y;
                const float xb0 = x.z * x.z, xb1 = x.w * x.w;
#pragma unroll
                for (int j = 0; j < 4; j++) {
                    float qa = Kg[j];
                    qa = fmaf(A0g[j], xa0, qa);
                    qa = fmaf(B0g[j], x.x, qa);
                    qa = fmaf(A1g[j], xa1, qa);
                    qa = fmaf(B1g[j], x.y, qa);
                    float qb = Kg[j];
                    qb = fmaf(A0g[j], xb0, qb);
                    qb = fmaf(B0g[j], x.z, qb);
                    qb = fmaf(A1g[j], xb1, qb);
                    qb = fmaf(B1g[j], x.w, qb);
                    float ea, eb;
                    asm("ex2.approx.ftz.f32 %0, %1;" : "=f"(ea) : "f"(qa));
                    asm("ex2.approx.ftz.f32 %0, %1;" : "=f"(eb) : "f"(qb));
                    ac[j] = fmaf(m.x, ea, ac[j]);
                    ac[j] = fmaf(m.y, eb, ac[j]);
                }
            }
#pragma unroll
            for (int off = 16; off > 0; off >>= 1) {
#pragma unroll
                for (int j = 0; j < 4; j++)
                    ac[j] += __shfl_xor_sync(0xffffffffu, ac[j], off);
            }
            if (lane == 0) {
#pragma unroll
                for (int j = 0; j < 4; j++)
                    partial[warp][4 * pass + j] = ac[j];
            }
        }
    }

    __syncthreads();

    // Combine 8 warp partials -> 8 outputs for this block
    if (tid < 8) {
        float v = 0.0f;
#pragma unroll
        for (int w = 0; w < 8; w++)
            v += partial[w][tid];
        out[b * NN + n0 + tid] = v;
    }
}

extern "C" void kernel_launch(void* const* d_in, const int* in_sizes, int n_in,
                              void* d_out, int out_size) {
    const float* batch   = (const float*)d_in[0];   // [B,P,D] f32
    const float* mask    = (const float*)d_in[1];   // [B,P]   f32
    const float* centers = (const float*)d_in[2];   // [N,D]   f32
    const float* sharp   = (const float*)d_in[3];   // [N,D]   f32
    float* out = (float*)d_out;                     // [B,N]   f32

    slayer_fused<<<BB * 8, 256>>>((const float4*)batch, (const float2*)mask,
                                  centers, sharp, out);
}